// round 5
// baseline (speedup 1.0000x reference)
#include <cuda_runtime.h>
#include <math.h>
#include <stdint.h>

// ----------------------------------------------------------------------------
// Problem constants
// ----------------------------------------------------------------------------
#define B_   2
#define L_   2048
#define DIM_ 1024
#define H_   16
#define D_   64
#define BL_  (B_ * L_)         // 4096
#define BH_  (B_ * H_)         // 32

// Scratch (device globals — allocation-free per harness rules)
__device__ float g_qkv[BL_ * 3 * DIM_];                // [4096, 3072]
__device__ float g_q[BH_ * L_ * D_];                   // [B,H,L,D]
__device__ float g_k[BH_ * L_ * D_];
__device__ float g_v[BH_ * L_ * D_];
__device__ float g_o[BL_ * DIM_];                      // [B,L,H,D] == [B,L,DIM]

// ----------------------------------------------------------------------------
// SGEMM: C[M,N] = A[M,K] @ B[K,N] (+ bias[N]), row-major, tiles 128x128x16
// ----------------------------------------------------------------------------
__global__ __launch_bounds__(256) void sgemm128(
    const float* __restrict__ A, const float* __restrict__ Bm,
    const float* __restrict__ bias, float* __restrict__ C,
    int M, int N, int K)
{
    __shared__ float As[16][128];   // [k][m]
    __shared__ float Bs[16][128];   // [k][n]

    const int tid = threadIdx.x;
    const int tx = tid & 15;
    const int ty = tid >> 4;
    const int row0 = blockIdx.y * 128;
    const int col0 = blockIdx.x * 128;

    float acc[8][8];
#pragma unroll
    for (int i = 0; i < 8; i++)
#pragma unroll
        for (int j = 0; j < 8; j++) acc[i][j] = 0.f;

    for (int k0 = 0; k0 < K; k0 += 16) {
#pragma unroll
        for (int it = 0; it < 2; it++) {
            int idx = tid + it * 256;       // 0..511
            int r = idx >> 2;               // 0..127
            int kq = idx & 3;               // 0..3
            float4 a = *(const float4*)(A + (size_t)(row0 + r) * K + k0 + kq * 4);
            As[kq * 4 + 0][r] = a.x;
            As[kq * 4 + 1][r] = a.y;
            As[kq * 4 + 2][r] = a.z;
            As[kq * 4 + 3][r] = a.w;
        }
#pragma unroll
        for (int it = 0; it < 2; it++) {
            int idx = tid + it * 256;
            int kr = idx >> 5;              // 0..15
            int cq = idx & 31;              // 0..31
            *(float4*)(&Bs[kr][cq * 4]) =
                *(const float4*)(Bm + (size_t)(k0 + kr) * N + col0 + cq * 4);
        }
        __syncthreads();

#pragma unroll
        for (int k = 0; k < 16; k++) {
            float a[8], b[8];
            *(float4*)(a)     = *(float4*)(&As[k][ty * 8]);
            *(float4*)(a + 4) = *(float4*)(&As[k][ty * 8 + 4]);
            *(float4*)(b)     = *(float4*)(&Bs[k][tx * 8]);
            *(float4*)(b + 4) = *(float4*)(&Bs[k][tx * 8 + 4]);
#pragma unroll
            for (int i = 0; i < 8; i++)
#pragma unroll
                for (int j = 0; j < 8; j++) acc[i][j] += a[i] * b[j];
        }
        __syncthreads();
    }

#pragma unroll
    for (int i = 0; i < 8; i++) {
        int r = row0 + ty * 8 + i;
#pragma unroll
        for (int j = 0; j < 8; j += 4) {
            int c = col0 + tx * 8 + j;
            float4 v;
            v.x = acc[i][j + 0];
            v.y = acc[i][j + 1];
            v.z = acc[i][j + 2];
            v.w = acc[i][j + 3];
            if (bias) {
                v.x += bias[c + 0];
                v.y += bias[c + 1];
                v.z += bias[c + 2];
                v.w += bias[c + 3];
            }
            *(float4*)(C + (size_t)r * N + c) = v;
        }
    }
}

// ----------------------------------------------------------------------------
// RMSNorm (over D=64) + RoPE; split qkv into q/k/v in [B,H,L,D].
// ----------------------------------------------------------------------------
__global__ __launch_bounds__(256) void rmsrope_kernel(
    const float* __restrict__ qkv, const float* __restrict__ pe,
    const float* __restrict__ qscale, const float* __restrict__ kscale,
    float* __restrict__ q, float* __restrict__ k, float* __restrict__ v)
{
    const int warp = (blockIdx.x * blockDim.x + threadIdx.x) >> 5;  // 0..65535
    const int lane = threadIdx.x & 31;
    const int b = warp >> 15;
    const int rem = warp & 32767;
    const int h = rem >> 11;
    const int l = rem & 2047;

    const float* base = qkv + ((size_t)(b * L_ + l)) * (3 * DIM_) + h * D_;
    float2 q2 = *(const float2*)(base + lane * 2);
    float2 k2 = *(const float2*)(base + DIM_ + lane * 2);
    float2 v2 = *(const float2*)(base + 2 * DIM_ + lane * 2);

    float sq = q2.x * q2.x + q2.y * q2.y;
    float sk = k2.x * k2.x + k2.y * k2.y;
#pragma unroll
    for (int o = 16; o > 0; o >>= 1) {
        sq += __shfl_xor_sync(0xffffffffu, sq, o);
        sk += __shfl_xor_sync(0xffffffffu, sk, o);
    }
    const float qinv = rsqrtf(sq * (1.f / 64.f) + 1e-6f);
    const float kinv = rsqrtf(sk * (1.f / 64.f) + 1e-6f);

    float2 qsc = *(const float2*)(qscale + lane * 2);
    float2 ksc = *(const float2*)(kscale + lane * 2);
    float t0 = q2.x * qinv * qsc.x;
    float t1 = q2.y * qinv * qsc.y;
    float u0 = k2.x * kinv * ksc.x;
    float u1 = k2.y * kinv * ksc.y;

    float4 p = *(const float4*)(pe + (((size_t)(b * L_ + l)) * 32 + lane) * 4);
    float2 qo, ko;
    qo.x = p.x * t0 + p.y * t1;
    qo.y = p.z * t0 + p.w * t1;
    ko.x = p.x * u0 + p.y * u1;
    ko.y = p.z * u0 + p.w * u1;

    const size_t orow = ((size_t)((b * H_ + h) * L_ + l)) * D_;
    *(float2*)(q + orow + lane * 2) = qo;
    *(float2*)(k + orow + lane * 2) = ko;
    *(float2*)(v + orow + lane * 2) = v2;
}

// ----------------------------------------------------------------------------
// Flash attention with tf32 tensor-core MMA (mma.sync.m16n8k8).
// Block = 128 threads (4 warps). 64 queries/block; warp w owns query rows
// [16w, 16w+16). Iterates over key tiles of 64. Softmax fully in registers
// (each row lives in one 4-lane quad). P re-fragmented through per-warp smem.
// Output written directly in [B,L,H,D].
// ----------------------------------------------------------------------------
#define PAD 68
#define SK_OFF   0
#define SV_OFF   (64 * PAD)
#define SP_OFF   (2 * 64 * PAD)
#define ATTN_SMEM_FLOATS (3 * 64 * PAD)
#define ATTN_SMEM_BYTES  (ATTN_SMEM_FLOATS * 4)

__device__ __forceinline__ uint32_t f2tf32(float x) {
    uint32_t r;
    asm("cvt.rna.tf32.f32 %0, %1;" : "=r"(r) : "f"(x));
    return r;
}

__device__ __forceinline__ void mma_tf32(float* d, const uint32_t* a,
                                         uint32_t b0, uint32_t b1) {
    asm volatile(
        "mma.sync.aligned.m16n8k8.row.col.f32.tf32.tf32.f32 "
        "{%0,%1,%2,%3}, {%4,%5,%6,%7}, {%8,%9}, {%0,%1,%2,%3};\n"
        : "+f"(d[0]), "+f"(d[1]), "+f"(d[2]), "+f"(d[3])
        : "r"(a[0]), "r"(a[1]), "r"(a[2]), "r"(a[3]), "r"(b0), "r"(b1));
}

__global__ __launch_bounds__(128) void attn_mma(
    const float* __restrict__ q, const float* __restrict__ k,
    const float* __restrict__ v, float* __restrict__ o)
{
    extern __shared__ float sm[];
    float* sK = sm + SK_OFF;            // [64][PAD] tf32 bits
    float* sV = sm + SV_OFF;            // [64][PAD] tf32 bits
    float* sP = sm + SP_OFF;            // 4 warps x [16][PAD] tf32 bits

    const int tid  = threadIdx.x;
    const int lane = tid & 31;
    const int warp = tid >> 5;          // 0..3
    const int gid  = lane >> 2;         // 0..7
    const int tig  = lane & 3;          // 0..3
    const int bh = blockIdx.y;
    const int q0 = blockIdx.x * 64;
    const size_t bhoff = (size_t)bh * L_ * D_;
    const float* Q = q + bhoff;
    const float* K = k + bhoff;
    const float* V = v + bhoff;

    // scale folds 1/sqrt(D) and log2(e) so softmax uses exp2
    const float QSCALE = 0.125f * 1.4426950408889634f;

    // ---- Q fragments (A operand), held for whole block ----
    const int r0 = q0 + warp * 16 + gid;   // row of a0/a2
    uint32_t qf[8][4];
#pragma unroll
    for (int kk = 0; kk < 8; kk++) {
        qf[kk][0] = f2tf32(Q[(size_t)r0 * D_ + kk * 8 + tig] * QSCALE);
        qf[kk][1] = f2tf32(Q[(size_t)(r0 + 8) * D_ + kk * 8 + tig] * QSCALE);
        qf[kk][2] = f2tf32(Q[(size_t)r0 * D_ + kk * 8 + tig + 4] * QSCALE);
        qf[kk][3] = f2tf32(Q[(size_t)(r0 + 8) * D_ + kk * 8 + tig + 4] * QSCALE);
    }

    float of[8][4];
#pragma unroll
    for (int nt = 0; nt < 8; nt++)
#pragma unroll
        for (int j = 0; j < 4; j++) of[nt][j] = 0.f;

    float m0 = -INFINITY, m1 = -INFINITY;   // running max (rows gid, gid+8)
    float l0 = 0.f, l1 = 0.f;               // running sum (this lane's cols)

    uint32_t* sPw = (uint32_t*)(sP + warp * 16 * PAD);

    for (int c0 = 0; c0 < L_; c0 += 64) {
        // ---- load K,V tile -> smem as tf32 bits ----
#pragma unroll
        for (int it = 0; it < 8; it++) {
            int idx = tid + it * 128;       // 0..1023
            int r = idx >> 4;
            int c4 = idx & 15;
            float4 a = *(const float4*)(K + (size_t)(c0 + r) * D_ + c4 * 4);
            uint4 ua = {f2tf32(a.x), f2tf32(a.y), f2tf32(a.z), f2tf32(a.w)};
            *(uint4*)(&sK[r * PAD + c4 * 4]) = ua;
            float4 bv = *(const float4*)(V + (size_t)(c0 + r) * D_ + c4 * 4);
            uint4 ub = {f2tf32(bv.x), f2tf32(bv.y), f2tf32(bv.z), f2tf32(bv.w)};
            *(uint4*)(&sV[r * PAD + c4 * 4]) = ub;
        }
        __syncthreads();

        // ---- S = Q K^T  (warp's 16 rows x 64 cols) ----
        float sf[8][4];
#pragma unroll
        for (int nt = 0; nt < 8; nt++)
#pragma unroll
            for (int j = 0; j < 4; j++) sf[nt][j] = 0.f;

        const uint32_t* sKu = (const uint32_t*)sK;
#pragma unroll
        for (int kk = 0; kk < 8; kk++) {
#pragma unroll
            for (int nt = 0; nt < 8; nt++) {
                uint32_t b0 = sKu[(nt * 8 + gid) * PAD + kk * 8 + tig];
                uint32_t b1 = sKu[(nt * 8 + gid) * PAD + kk * 8 + tig + 4];
                mma_tf32(sf[nt], qf[kk], b0, b1);
            }
        }

        // ---- online softmax in registers ----
        float mn0 = m0, mn1 = m1;
#pragma unroll
        for (int nt = 0; nt < 8; nt++) {
            mn0 = fmaxf(mn0, fmaxf(sf[nt][0], sf[nt][1]));
            mn1 = fmaxf(mn1, fmaxf(sf[nt][2], sf[nt][3]));
        }
        mn0 = fmaxf(mn0, __shfl_xor_sync(0xffffffffu, mn0, 1));
        mn0 = fmaxf(mn0, __shfl_xor_sync(0xffffffffu, mn0, 2));
        mn1 = fmaxf(mn1, __shfl_xor_sync(0xffffffffu, mn1, 1));
        mn1 = fmaxf(mn1, __shfl_xor_sync(0xffffffffu, mn1, 2));
        float a0 = exp2f(m0 - mn0);
        float a1 = exp2f(m1 - mn1);
        m0 = mn0; m1 = mn1;
        l0 *= a0; l1 *= a1;

#pragma unroll
        for (int nt = 0; nt < 8; nt++) {
            float p00 = exp2f(sf[nt][0] - m0);
            float p01 = exp2f(sf[nt][1] - m0);
            float p10 = exp2f(sf[nt][2] - m1);
            float p11 = exp2f(sf[nt][3] - m1);
            l0 += p00 + p01;
            l1 += p10 + p11;
            uint2 u0 = {f2tf32(p00), f2tf32(p01)};
            uint2 u1 = {f2tf32(p10), f2tf32(p11)};
            *(uint2*)(&sPw[gid * PAD + nt * 8 + 2 * tig]) = u0;
            *(uint2*)(&sPw[(gid + 8) * PAD + nt * 8 + 2 * tig]) = u1;
            // rescale O accumulators
            of[nt][0] *= a0; of[nt][1] *= a0;
            of[nt][2] *= a1; of[nt][3] *= a1;
        }
        __syncwarp();

        // ---- O += P @ V ----
        const uint32_t* sVu = (const uint32_t*)sV;
#pragma unroll
        for (int kk = 0; kk < 8; kk++) {
            uint32_t af[4];
            af[0] = sPw[gid * PAD + kk * 8 + tig];
            af[1] = sPw[(gid + 8) * PAD + kk * 8 + tig];
            af[2] = sPw[gid * PAD + kk * 8 + tig + 4];
            af[3] = sPw[(gid + 8) * PAD + kk * 8 + tig + 4];
#pragma unroll
            for (int nt = 0; nt < 8; nt++) {
                uint32_t b0 = sVu[(kk * 8 + tig) * PAD + nt * 8 + gid];
                uint32_t b1 = sVu[(kk * 8 + tig + 4) * PAD + nt * 8 + gid];
                mma_tf32(of[nt], af, b0, b1);
            }
        }
        __syncthreads();
    }

    // ---- epilogue: finish l, normalize, write [B,L,H,D] ----
    l0 += __shfl_xor_sync(0xffffffffu, l0, 1);
    l0 += __shfl_xor_sync(0xffffffffu, l0, 2);
    l1 += __shfl_xor_sync(0xffffffffu, l1, 1);
    l1 += __shfl_xor_sync(0xffffffffu, l1, 2);
    const float inv0 = 1.f / l0;
    const float inv1 = 1.f / l1;

    const int b = bh >> 4;
    const int h = bh & 15;
    float* orow0 = o + (((size_t)(b * L_ + r0)) * H_ + h) * D_;
    float* orow1 = o + (((size_t)(b * L_ + r0 + 8)) * H_ + h) * D_;
#pragma unroll
    for (int nt = 0; nt < 8; nt++) {
        float2 v0 = {of[nt][0] * inv0, of[nt][1] * inv0};
        float2 v1 = {of[nt][2] * inv1, of[nt][3] * inv1};
        *(float2*)(orow0 + nt * 8 + 2 * tig) = v0;
        *(float2*)(orow1 + nt * 8 + 2 * tig) = v1;
    }
}

// ----------------------------------------------------------------------------
// Launch
// ----------------------------------------------------------------------------
extern "C" void kernel_launch(void* const* d_in, const int* in_sizes, int n_in,
                              void* d_out, int out_size)
{
    const float* x      = (const float*)d_in[0];
    const float* pe     = (const float*)d_in[1];
    const float* w_qkv  = (const float*)d_in[2];
    const float* qscale = (const float*)d_in[3];
    const float* kscale = (const float*)d_in[4];
    const float* w_proj = (const float*)d_in[5];
    const float* b_proj = (const float*)d_in[6];
    float* out = (float*)d_out;

    float *p_qkv, *p_q, *p_k, *p_v, *p_o;
    cudaGetSymbolAddress((void**)&p_qkv, g_qkv);
    cudaGetSymbolAddress((void**)&p_q, g_q);
    cudaGetSymbolAddress((void**)&p_k, g_k);
    cudaGetSymbolAddress((void**)&p_v, g_v);
    cudaGetSymbolAddress((void**)&p_o, g_o);

    cudaFuncSetAttribute(attn_mma, cudaFuncAttributeMaxDynamicSharedMemorySize,
                         ATTN_SMEM_BYTES);

    // 1. QKV GEMM: [4096,1024] @ [1024,3072]
    {
        dim3 grid(3 * DIM_ / 128, BL_ / 128);
        sgemm128<<<grid, 256>>>(x, w_qkv, nullptr, p_qkv, BL_, 3 * DIM_, DIM_);
    }
    // 2. RMSNorm + RoPE + split
    {
        int warps = B_ * H_ * L_;              // 65536
        rmsrope_kernel<<<warps * 32 / 256, 256>>>(p_qkv, pe, qscale, kscale,
                                                  p_q, p_k, p_v);
    }
    // 3. Attention (tf32 tensor cores)
    {
        dim3 grid(L_ / 64, BH_);
        attn_mma<<<grid, 128, ATTN_SMEM_BYTES>>>(p_q, p_k, p_v, p_o);
    }
    // 4. Output projection: [4096,1024] @ [1024,1024] + bias
    {
        dim3 grid(DIM_ / 128, BL_ / 128);
        sgemm128<<<grid, 256>>>(p_o, w_proj, b_proj, out, BL_, DIM_, DIM_);
    }
}

// round 6
// speedup vs baseline: 1.0009x; 1.0009x over previous
#include <cuda_runtime.h>
#include <math.h>
#include <stdint.h>

// ----------------------------------------------------------------------------
// Problem constants
// ----------------------------------------------------------------------------
#define B_   2
#define L_   2048
#define DIM_ 1024
#define H_   16
#define D_   64
#define BL_  (B_ * L_)         // 4096
#define BH_  (B_ * H_)         // 32

// Scratch (device globals — allocation-free per harness rules)
__device__ float g_qkv[BL_ * 3 * DIM_];                // [4096, 3072]
__device__ float g_q[BH_ * L_ * D_];                   // [B,H,L,D]
__device__ float g_k[BH_ * L_ * D_];
__device__ float g_v[BH_ * L_ * D_];
__device__ float g_o[BL_ * DIM_];                      // [B,L,H,D] == [B,L,DIM]

// ----------------------------------------------------------------------------
// SGEMM: C[M,N] = A[M,K] @ B[K,N] (+ bias[N]), row-major, tiles 128x128x16
// ----------------------------------------------------------------------------
__global__ __launch_bounds__(256) void sgemm128(
    const float* __restrict__ A, const float* __restrict__ Bm,
    const float* __restrict__ bias, float* __restrict__ C,
    int M, int N, int K)
{
    __shared__ float As[16][128];   // [k][m]
    __shared__ float Bs[16][128];   // [k][n]

    const int tid = threadIdx.x;
    const int tx = tid & 15;
    const int ty = tid >> 4;
    const int row0 = blockIdx.y * 128;
    const int col0 = blockIdx.x * 128;

    float acc[8][8];
#pragma unroll
    for (int i = 0; i < 8; i++)
#pragma unroll
        for (int j = 0; j < 8; j++) acc[i][j] = 0.f;

    for (int k0 = 0; k0 < K; k0 += 16) {
#pragma unroll
        for (int it = 0; it < 2; it++) {
            int idx = tid + it * 256;       // 0..511
            int r = idx >> 2;               // 0..127
            int kq = idx & 3;               // 0..3
            float4 a = *(const float4*)(A + (size_t)(row0 + r) * K + k0 + kq * 4);
            As[kq * 4 + 0][r] = a.x;
            As[kq * 4 + 1][r] = a.y;
            As[kq * 4 + 2][r] = a.z;
            As[kq * 4 + 3][r] = a.w;
        }
#pragma unroll
        for (int it = 0; it < 2; it++) {
            int idx = tid + it * 256;
            int kr = idx >> 5;              // 0..15
            int cq = idx & 31;              // 0..31
            *(float4*)(&Bs[kr][cq * 4]) =
                *(const float4*)(Bm + (size_t)(k0 + kr) * N + col0 + cq * 4);
        }
        __syncthreads();

#pragma unroll
        for (int k = 0; k < 16; k++) {
            float a[8], b[8];
            *(float4*)(a)     = *(float4*)(&As[k][ty * 8]);
            *(float4*)(a + 4) = *(float4*)(&As[k][ty * 8 + 4]);
            *(float4*)(b)     = *(float4*)(&Bs[k][tx * 8]);
            *(float4*)(b + 4) = *(float4*)(&Bs[k][tx * 8 + 4]);
#pragma unroll
            for (int i = 0; i < 8; i++)
#pragma unroll
                for (int j = 0; j < 8; j++) acc[i][j] += a[i] * b[j];
        }
        __syncthreads();
    }

#pragma unroll
    for (int i = 0; i < 8; i++) {
        int r = row0 + ty * 8 + i;
#pragma unroll
        for (int j = 0; j < 8; j += 4) {
            int c = col0 + tx * 8 + j;
            float4 v;
            v.x = acc[i][j + 0];
            v.y = acc[i][j + 1];
            v.z = acc[i][j + 2];
            v.w = acc[i][j + 3];
            if (bias) {
                v.x += bias[c + 0];
                v.y += bias[c + 1];
                v.z += bias[c + 2];
                v.w += bias[c + 3];
            }
            *(float4*)(C + (size_t)r * N + c) = v;
        }
    }
}

// ----------------------------------------------------------------------------
// RMSNorm (over D=64) + RoPE; split qkv into q/k/v in [B,H,L,D].
// ----------------------------------------------------------------------------
__global__ __launch_bounds__(256) void rmsrope_kernel(
    const float* __restrict__ qkv, const float* __restrict__ pe,
    const float* __restrict__ qscale, const float* __restrict__ kscale,
    float* __restrict__ q, float* __restrict__ k, float* __restrict__ v)
{
    const int warp = (blockIdx.x * blockDim.x + threadIdx.x) >> 5;  // 0..65535
    const int lane = threadIdx.x & 31;
    const int b = warp >> 15;
    const int rem = warp & 32767;
    const int h = rem >> 11;
    const int l = rem & 2047;

    const float* base = qkv + ((size_t)(b * L_ + l)) * (3 * DIM_) + h * D_;
    float2 q2 = *(const float2*)(base + lane * 2);
    float2 k2 = *(const float2*)(base + DIM_ + lane * 2);
    float2 v2 = *(const float2*)(base + 2 * DIM_ + lane * 2);

    float sq = q2.x * q2.x + q2.y * q2.y;
    float sk = k2.x * k2.x + k2.y * k2.y;
#pragma unroll
    for (int o = 16; o > 0; o >>= 1) {
        sq += __shfl_xor_sync(0xffffffffu, sq, o);
        sk += __shfl_xor_sync(0xffffffffu, sk, o);
    }
    const float qinv = rsqrtf(sq * (1.f / 64.f) + 1e-6f);
    const float kinv = rsqrtf(sk * (1.f / 64.f) + 1e-6f);

    float2 qsc = *(const float2*)(qscale + lane * 2);
    float2 ksc = *(const float2*)(kscale + lane * 2);
    float t0 = q2.x * qinv * qsc.x;
    float t1 = q2.y * qinv * qsc.y;
    float u0 = k2.x * kinv * ksc.x;
    float u1 = k2.y * kinv * ksc.y;

    float4 p = *(const float4*)(pe + (((size_t)(b * L_ + l)) * 32 + lane) * 4);
    float2 qo, ko;
    qo.x = p.x * t0 + p.y * t1;
    qo.y = p.z * t0 + p.w * t1;
    ko.x = p.x * u0 + p.y * u1;
    ko.y = p.z * u0 + p.w * u1;

    const size_t orow = ((size_t)((b * H_ + h) * L_ + l)) * D_;
    *(float2*)(q + orow + lane * 2) = qo;
    *(float2*)(k + orow + lane * 2) = ko;
    *(float2*)(v + orow + lane * 2) = v2;
}

// ----------------------------------------------------------------------------
// Flash attention with tf32 tensor-core MMA (mma.sync.m16n8k8).
// Block = 128 threads (4 warps). 64 queries/block; warp w owns query rows
// [16w, 16w+16). Iterates over key tiles of 64. Softmax fully in registers
// (each row lives in one 4-lane quad). P re-fragmented through per-warp smem.
// Output written directly in [B,L,H,D].
// ----------------------------------------------------------------------------
#define PAD 68
#define SK_OFF   0
#define SV_OFF   (64 * PAD)
#define SP_OFF   (2 * 64 * PAD)
#define ATTN_SMEM_FLOATS (3 * 64 * PAD)
#define ATTN_SMEM_BYTES  (ATTN_SMEM_FLOATS * 4)

__device__ __forceinline__ uint32_t f2tf32(float x) {
    uint32_t r;
    asm("cvt.rna.tf32.f32 %0, %1;" : "=r"(r) : "f"(x));
    return r;
}

__device__ __forceinline__ void mma_tf32(float* d, const uint32_t* a,
                                         uint32_t b0, uint32_t b1) {
    asm volatile(
        "mma.sync.aligned.m16n8k8.row.col.f32.tf32.tf32.f32 "
        "{%0,%1,%2,%3}, {%4,%5,%6,%7}, {%8,%9}, {%0,%1,%2,%3};\n"
        : "+f"(d[0]), "+f"(d[1]), "+f"(d[2]), "+f"(d[3])
        : "r"(a[0]), "r"(a[1]), "r"(a[2]), "r"(a[3]), "r"(b0), "r"(b1));
}

__global__ __launch_bounds__(128) void attn_mma(
    const float* __restrict__ q, const float* __restrict__ k,
    const float* __restrict__ v, float* __restrict__ o)
{
    extern __shared__ float sm[];
    float* sK = sm + SK_OFF;            // [64][PAD] tf32 bits
    float* sV = sm + SV_OFF;            // [64][PAD] tf32 bits
    float* sP = sm + SP_OFF;            // 4 warps x [16][PAD] tf32 bits

    const int tid  = threadIdx.x;
    const int lane = tid & 31;
    const int warp = tid >> 5;          // 0..3
    const int gid  = lane >> 2;         // 0..7
    const int tig  = lane & 3;          // 0..3
    const int bh = blockIdx.y;
    const int q0 = blockIdx.x * 64;
    const size_t bhoff = (size_t)bh * L_ * D_;
    const float* Q = q + bhoff;
    const float* K = k + bhoff;
    const float* V = v + bhoff;

    // scale folds 1/sqrt(D) and log2(e) so softmax uses exp2
    const float QSCALE = 0.125f * 1.4426950408889634f;

    // ---- Q fragments (A operand), held for whole block ----
    const int r0 = q0 + warp * 16 + gid;   // row of a0/a2
    uint32_t qf[8][4];
#pragma unroll
    for (int kk = 0; kk < 8; kk++) {
        qf[kk][0] = f2tf32(Q[(size_t)r0 * D_ + kk * 8 + tig] * QSCALE);
        qf[kk][1] = f2tf32(Q[(size_t)(r0 + 8) * D_ + kk * 8 + tig] * QSCALE);
        qf[kk][2] = f2tf32(Q[(size_t)r0 * D_ + kk * 8 + tig + 4] * QSCALE);
        qf[kk][3] = f2tf32(Q[(size_t)(r0 + 8) * D_ + kk * 8 + tig + 4] * QSCALE);
    }

    float of[8][4];
#pragma unroll
    for (int nt = 0; nt < 8; nt++)
#pragma unroll
        for (int j = 0; j < 4; j++) of[nt][j] = 0.f;

    float m0 = -INFINITY, m1 = -INFINITY;   // running max (rows gid, gid+8)
    float l0 = 0.f, l1 = 0.f;               // running sum (this lane's cols)

    uint32_t* sPw = (uint32_t*)(sP + warp * 16 * PAD);

    for (int c0 = 0; c0 < L_; c0 += 64) {
        // ---- load K,V tile -> smem as tf32 bits ----
#pragma unroll
        for (int it = 0; it < 8; it++) {
            int idx = tid + it * 128;       // 0..1023
            int r = idx >> 4;
            int c4 = idx & 15;
            float4 a = *(const float4*)(K + (size_t)(c0 + r) * D_ + c4 * 4);
            uint4 ua = {f2tf32(a.x), f2tf32(a.y), f2tf32(a.z), f2tf32(a.w)};
            *(uint4*)(&sK[r * PAD + c4 * 4]) = ua;
            float4 bv = *(const float4*)(V + (size_t)(c0 + r) * D_ + c4 * 4);
            uint4 ub = {f2tf32(bv.x), f2tf32(bv.y), f2tf32(bv.z), f2tf32(bv.w)};
            *(uint4*)(&sV[r * PAD + c4 * 4]) = ub;
        }
        __syncthreads();

        // ---- S = Q K^T  (warp's 16 rows x 64 cols) ----
        float sf[8][4];
#pragma unroll
        for (int nt = 0; nt < 8; nt++)
#pragma unroll
            for (int j = 0; j < 4; j++) sf[nt][j] = 0.f;

        const uint32_t* sKu = (const uint32_t*)sK;
#pragma unroll
        for (int kk = 0; kk < 8; kk++) {
#pragma unroll
            for (int nt = 0; nt < 8; nt++) {
                uint32_t b0 = sKu[(nt * 8 + gid) * PAD + kk * 8 + tig];
                uint32_t b1 = sKu[(nt * 8 + gid) * PAD + kk * 8 + tig + 4];
                mma_tf32(sf[nt], qf[kk], b0, b1);
            }
        }

        // ---- online softmax in registers ----
        float mn0 = m0, mn1 = m1;
#pragma unroll
        for (int nt = 0; nt < 8; nt++) {
            mn0 = fmaxf(mn0, fmaxf(sf[nt][0], sf[nt][1]));
            mn1 = fmaxf(mn1, fmaxf(sf[nt][2], sf[nt][3]));
        }
        mn0 = fmaxf(mn0, __shfl_xor_sync(0xffffffffu, mn0, 1));
        mn0 = fmaxf(mn0, __shfl_xor_sync(0xffffffffu, mn0, 2));
        mn1 = fmaxf(mn1, __shfl_xor_sync(0xffffffffu, mn1, 1));
        mn1 = fmaxf(mn1, __shfl_xor_sync(0xffffffffu, mn1, 2));
        float a0 = exp2f(m0 - mn0);
        float a1 = exp2f(m1 - mn1);
        m0 = mn0; m1 = mn1;
        l0 *= a0; l1 *= a1;

#pragma unroll
        for (int nt = 0; nt < 8; nt++) {
            float p00 = exp2f(sf[nt][0] - m0);
            float p01 = exp2f(sf[nt][1] - m0);
            float p10 = exp2f(sf[nt][2] - m1);
            float p11 = exp2f(sf[nt][3] - m1);
            l0 += p00 + p01;
            l1 += p10 + p11;
            uint2 u0 = {f2tf32(p00), f2tf32(p01)};
            uint2 u1 = {f2tf32(p10), f2tf32(p11)};
            *(uint2*)(&sPw[gid * PAD + nt * 8 + 2 * tig]) = u0;
            *(uint2*)(&sPw[(gid + 8) * PAD + nt * 8 + 2 * tig]) = u1;
            // rescale O accumulators
            of[nt][0] *= a0; of[nt][1] *= a0;
            of[nt][2] *= a1; of[nt][3] *= a1;
        }
        __syncwarp();

        // ---- O += P @ V ----
        const uint32_t* sVu = (const uint32_t*)sV;
#pragma unroll
        for (int kk = 0; kk < 8; kk++) {
            uint32_t af[4];
            af[0] = sPw[gid * PAD + kk * 8 + tig];
            af[1] = sPw[(gid + 8) * PAD + kk * 8 + tig];
            af[2] = sPw[gid * PAD + kk * 8 + tig + 4];
            af[3] = sPw[(gid + 8) * PAD + kk * 8 + tig + 4];
#pragma unroll
            for (int nt = 0; nt < 8; nt++) {
                uint32_t b0 = sVu[(kk * 8 + tig) * PAD + nt * 8 + gid];
                uint32_t b1 = sVu[(kk * 8 + tig + 4) * PAD + nt * 8 + gid];
                mma_tf32(of[nt], af, b0, b1);
            }
        }
        __syncthreads();
    }

    // ---- epilogue: finish l, normalize, write [B,L,H,D] ----
    l0 += __shfl_xor_sync(0xffffffffu, l0, 1);
    l0 += __shfl_xor_sync(0xffffffffu, l0, 2);
    l1 += __shfl_xor_sync(0xffffffffu, l1, 1);
    l1 += __shfl_xor_sync(0xffffffffu, l1, 2);
    const float inv0 = 1.f / l0;
    const float inv1 = 1.f / l1;

    const int b = bh >> 4;
    const int h = bh & 15;
    float* orow0 = o + (((size_t)(b * L_ + r0)) * H_ + h) * D_;
    float* orow1 = o + (((size_t)(b * L_ + r0 + 8)) * H_ + h) * D_;
#pragma unroll
    for (int nt = 0; nt < 8; nt++) {
        float2 v0 = {of[nt][0] * inv0, of[nt][1] * inv0};
        float2 v1 = {of[nt][2] * inv1, of[nt][3] * inv1};
        *(float2*)(orow0 + nt * 8 + 2 * tig) = v0;
        *(float2*)(orow1 + nt * 8 + 2 * tig) = v1;
    }
}

// ----------------------------------------------------------------------------
// Launch
// ----------------------------------------------------------------------------
extern "C" void kernel_launch(void* const* d_in, const int* in_sizes, int n_in,
                              void* d_out, int out_size)
{
    const float* x      = (const float*)d_in[0];
    const float* pe     = (const float*)d_in[1];
    const float* w_qkv  = (const float*)d_in[2];
    const float* qscale = (const float*)d_in[3];
    const float* kscale = (const float*)d_in[4];
    const float* w_proj = (const float*)d_in[5];
    const float* b_proj = (const float*)d_in[6];
    float* out = (float*)d_out;

    float *p_qkv, *p_q, *p_k, *p_v, *p_o;
    cudaGetSymbolAddress((void**)&p_qkv, g_qkv);
    cudaGetSymbolAddress((void**)&p_q, g_q);
    cudaGetSymbolAddress((void**)&p_k, g_k);
    cudaGetSymbolAddress((void**)&p_v, g_v);
    cudaGetSymbolAddress((void**)&p_o, g_o);

    cudaFuncSetAttribute(attn_mma, cudaFuncAttributeMaxDynamicSharedMemorySize,
                         ATTN_SMEM_BYTES);

    // 1. QKV GEMM: [4096,1024] @ [1024,3072]
    {
        dim3 grid(3 * DIM_ / 128, BL_ / 128);
        sgemm128<<<grid, 256>>>(x, w_qkv, nullptr, p_qkv, BL_, 3 * DIM_, DIM_);
    }
    // 2. RMSNorm + RoPE + split
    {
        int warps = B_ * H_ * L_;              // 65536
        rmsrope_kernel<<<warps * 32 / 256, 256>>>(p_qkv, pe, qscale, kscale,
                                                  p_q, p_k, p_v);
    }
    // 3. Attention (tf32 tensor cores)
    {
        dim3 grid(L_ / 64, BH_);
        attn_mma<<<grid, 128, ATTN_SMEM_BYTES>>>(p_q, p_k, p_v, p_o);
    }
    // 4. Output projection: [4096,1024] @ [1024,1024] + bias
    {
        dim3 grid(DIM_ / 128, BL_ / 128);
        sgemm128<<<grid, 256>>>(p_o, w_proj, b_proj, out, BL_, DIM_, DIM_);
    }
}

// round 7
// speedup vs baseline: 1.1427x; 1.1416x over previous
#include <cuda_runtime.h>
#include <math.h>
#include <stdint.h>

// ----------------------------------------------------------------------------
// Problem constants
// ----------------------------------------------------------------------------
#define B_   2
#define L_   2048
#define DIM_ 1024
#define H_   16
#define D_   64
#define BL_  (B_ * L_)         // 4096
#define BH_  (B_ * H_)         // 32

// Scratch (device globals — allocation-free per harness rules)
__device__ float g_qkv[BL_ * 3 * DIM_];                // [4096, 3072]
__device__ float g_q[BH_ * L_ * D_];                   // [B,H,L,D]
__device__ float g_k[BH_ * L_ * D_];
__device__ float g_v[BH_ * L_ * D_];
__device__ float g_o[BL_ * DIM_];                      // [B,L,H,D] == [B,L,DIM]

// ----------------------------------------------------------------------------
// tf32 helpers
// ----------------------------------------------------------------------------
__device__ __forceinline__ uint32_t f2tf32(float x) {
    uint32_t r;
    asm("cvt.rna.tf32.f32 %0, %1;" : "=r"(r) : "f"(x));
    return r;
}

__device__ __forceinline__ void mma_tf32(float* d, const uint32_t* a,
                                         uint32_t b0, uint32_t b1) {
    asm volatile(
        "mma.sync.aligned.m16n8k8.row.col.f32.tf32.tf32.f32 "
        "{%0,%1,%2,%3}, {%4,%5,%6,%7}, {%8,%9}, {%0,%1,%2,%3};\n"
        : "+f"(d[0]), "+f"(d[1]), "+f"(d[2]), "+f"(d[3])
        : "r"(a[0]), "r"(a[1]), "r"(a[2]), "r"(a[3]), "r"(b0), "r"(b1));
}

// hi/lo split of a float4 into tf32 pair (hi = tf32(x), lo = tf32(x - hi))
__device__ __forceinline__ void split4(float4 v, float4& hi, float4& lo) {
    uint32_t hx = f2tf32(v.x), hy = f2tf32(v.y), hz = f2tf32(v.z), hw = f2tf32(v.w);
    hi.x = __uint_as_float(hx); hi.y = __uint_as_float(hy);
    hi.z = __uint_as_float(hz); hi.w = __uint_as_float(hw);
    lo.x = __uint_as_float(f2tf32(v.x - hi.x));
    lo.y = __uint_as_float(f2tf32(v.y - hi.y));
    lo.z = __uint_as_float(f2tf32(v.z - hi.z));
    lo.w = __uint_as_float(f2tf32(v.w - hi.w));
}

// ----------------------------------------------------------------------------
// Split-tf32 GEMM: C[M,N] = A[M,K] @ B[K,N] (+ bias[N]), full fp32 accuracy
// via 3-term compensation (AhBh + AhBl + AlBh). Tiles 128x128x32, 8 warps,
// warp tile 64x32 (4x m16, 4x n8 per k8 step).
// A smem [m][36] (pad 36 -> 4*gid+tig distinct banks);
// B smem [k][136] (pad 136 -> 8*tig+gid distinct banks).
// ----------------------------------------------------------------------------
#define GA_PAD 36
#define GB_PAD 136
#define G_SAH 0
#define G_SAL (128 * GA_PAD)
#define G_SBH (2 * 128 * GA_PAD)
#define G_SBL (2 * 128 * GA_PAD + 32 * GB_PAD)
#define GEMM_SMEM_FLOATS (2 * 128 * GA_PAD + 2 * 32 * GB_PAD)
#define GEMM_SMEM_BYTES  (GEMM_SMEM_FLOATS * 4)

__global__ __launch_bounds__(256, 1) void gemm_tf32s(
    const float* __restrict__ A, const float* __restrict__ Bm,
    const float* __restrict__ bias, float* __restrict__ C,
    int M, int N, int K)
{
    extern __shared__ float sm[];
    float* sAH = sm + G_SAH;
    float* sAL = sm + G_SAL;
    float* sBH = sm + G_SBH;
    float* sBL = sm + G_SBL;

    const int tid  = threadIdx.x;
    const int lane = tid & 31;
    const int warp = tid >> 5;
    const int gid  = lane >> 2;
    const int tig  = lane & 3;
    const int warpm = warp & 1;        // 2 m-strips of 64
    const int warpn = warp >> 1;       // 4 n-strips of 32
    const int row0 = blockIdx.y * 128;
    const int col0 = blockIdx.x * 128;

    // staging roles
    const int am  = tid & 127;         // A row
    const int akq = tid >> 7;          // A float4-col base (0/1)
    const int bn4 = tid & 31;          // B float4 col (0..31)
    const int bkr = tid >> 5;          // B row base (0..7)

    float acc[4][4][4];
#pragma unroll
    for (int mt = 0; mt < 4; mt++)
#pragma unroll
        for (int nt = 0; nt < 4; nt++)
#pragma unroll
            for (int j = 0; j < 4; j++) acc[mt][nt][j] = 0.f;

    // prefetch chunk 0
    float4 pa[4], pb[4];
#pragma unroll
    for (int it = 0; it < 4; it++) {
        pa[it] = *(const float4*)(A + (size_t)(row0 + am) * K + (it * 2 + akq) * 4);
        pb[it] = *(const float4*)(Bm + (size_t)(bkr + it * 8) * N + col0 + bn4 * 4);
    }

    const int nchunks = K >> 5;
    for (int ch = 0; ch < nchunks; ch++) {
        // ---- convert + store staged chunk ----
#pragma unroll
        for (int it = 0; it < 4; it++) {
            float4 hi, lo;
            split4(pa[it], hi, lo);
            int kb = (it * 2 + akq) * 4;
            *(float4*)(&sAH[am * GA_PAD + kb]) = hi;
            *(float4*)(&sAL[am * GA_PAD + kb]) = lo;
            split4(pb[it], hi, lo);
            int kr = bkr + it * 8;
            *(float4*)(&sBH[kr * GB_PAD + bn4 * 4]) = hi;
            *(float4*)(&sBL[kr * GB_PAD + bn4 * 4]) = lo;
        }
        __syncthreads();

        // ---- prefetch next chunk (overlaps compute) ----
        if (ch + 1 < nchunks) {
            int kn = (ch + 1) * 32;
#pragma unroll
            for (int it = 0; it < 4; it++) {
                pa[it] = *(const float4*)(A + (size_t)(row0 + am) * K + kn + (it * 2 + akq) * 4);
                pb[it] = *(const float4*)(Bm + (size_t)(kn + bkr + it * 8) * N + col0 + bn4 * 4);
            }
        }

        // ---- compute: 4 k8 steps ----
        const uint32_t* uAH = (const uint32_t*)sAH;
        const uint32_t* uAL = (const uint32_t*)sAL;
        const uint32_t* uBH = (const uint32_t*)sBH;
        const uint32_t* uBL = (const uint32_t*)sBL;
#pragma unroll
        for (int ks = 0; ks < 4; ks++) {
            const int k0 = ks * 8;
            uint32_t ah[4][4], al[4][4];
#pragma unroll
            for (int mt = 0; mt < 4; mt++) {
                int r = (warpm * 64 + mt * 16 + gid) * GA_PAD + k0;
                ah[mt][0] = uAH[r + tig];
                ah[mt][1] = uAH[r + 8 * GA_PAD + tig];
                ah[mt][2] = uAH[r + tig + 4];
                ah[mt][3] = uAH[r + 8 * GA_PAD + tig + 4];
                al[mt][0] = uAL[r + tig];
                al[mt][1] = uAL[r + 8 * GA_PAD + tig];
                al[mt][2] = uAL[r + tig + 4];
                al[mt][3] = uAL[r + 8 * GA_PAD + tig + 4];
            }
#pragma unroll
            for (int nt = 0; nt < 4; nt++) {
                int c = warpn * 32 + nt * 8 + gid;
                uint32_t bh0 = uBH[(k0 + tig) * GB_PAD + c];
                uint32_t bh1 = uBH[(k0 + tig + 4) * GB_PAD + c];
                uint32_t bl0 = uBL[(k0 + tig) * GB_PAD + c];
                uint32_t bl1 = uBL[(k0 + tig + 4) * GB_PAD + c];
#pragma unroll
                for (int mt = 0; mt < 4; mt++) {
                    mma_tf32(acc[mt][nt], al[mt], bh0, bh1);   // Al*Bh
                    mma_tf32(acc[mt][nt], ah[mt], bl0, bl1);   // Ah*Bl
                    mma_tf32(acc[mt][nt], ah[mt], bh0, bh1);   // Ah*Bh
                }
            }
        }
        __syncthreads();
    }

    // ---- epilogue ----
#pragma unroll
    for (int mt = 0; mt < 4; mt++) {
        int gr = row0 + warpm * 64 + mt * 16 + gid;
#pragma unroll
        for (int nt = 0; nt < 4; nt++) {
            int gc = col0 + warpn * 32 + nt * 8 + 2 * tig;
            float b0 = 0.f, b1 = 0.f;
            if (bias) { b0 = bias[gc]; b1 = bias[gc + 1]; }
            float2 c01 = {acc[mt][nt][0] + b0, acc[mt][nt][1] + b1};
            float2 c23 = {acc[mt][nt][2] + b0, acc[mt][nt][3] + b1};
            *(float2*)(C + (size_t)gr * N + gc) = c01;
            *(float2*)(C + (size_t)(gr + 8) * N + gc) = c23;
        }
    }
}

// ----------------------------------------------------------------------------
// RMSNorm (over D=64) + RoPE; split qkv into q/k/v in [B,H,L,D].
// ----------------------------------------------------------------------------
__global__ __launch_bounds__(256) void rmsrope_kernel(
    const float* __restrict__ qkv, const float* __restrict__ pe,
    const float* __restrict__ qscale, const float* __restrict__ kscale,
    float* __restrict__ q, float* __restrict__ k, float* __restrict__ v)
{
    const int warp = (blockIdx.x * blockDim.x + threadIdx.x) >> 5;  // 0..65535
    const int lane = threadIdx.x & 31;
    const int b = warp >> 15;
    const int rem = warp & 32767;
    const int h = rem >> 11;
    const int l = rem & 2047;

    const float* base = qkv + ((size_t)(b * L_ + l)) * (3 * DIM_) + h * D_;
    float2 q2 = *(const float2*)(base + lane * 2);
    float2 k2 = *(const float2*)(base + DIM_ + lane * 2);
    float2 v2 = *(const float2*)(base + 2 * DIM_ + lane * 2);

    float sq = q2.x * q2.x + q2.y * q2.y;
    float sk = k2.x * k2.x + k2.y * k2.y;
#pragma unroll
    for (int o = 16; o > 0; o >>= 1) {
        sq += __shfl_xor_sync(0xffffffffu, sq, o);
        sk += __shfl_xor_sync(0xffffffffu, sk, o);
    }
    const float qinv = rsqrtf(sq * (1.f / 64.f) + 1e-6f);
    const float kinv = rsqrtf(sk * (1.f / 64.f) + 1e-6f);

    float2 qsc = *(const float2*)(qscale + lane * 2);
    float2 ksc = *(const float2*)(kscale + lane * 2);
    float t0 = q2.x * qinv * qsc.x;
    float t1 = q2.y * qinv * qsc.y;
    float u0 = k2.x * kinv * ksc.x;
    float u1 = k2.y * kinv * ksc.y;

    float4 p = *(const float4*)(pe + (((size_t)(b * L_ + l)) * 32 + lane) * 4);
    float2 qo, ko;
    qo.x = p.x * t0 + p.y * t1;
    qo.y = p.z * t0 + p.w * t1;
    ko.x = p.x * u0 + p.y * u1;
    ko.y = p.z * u0 + p.w * u1;

    const size_t orow = ((size_t)((b * H_ + h) * L_ + l)) * D_;
    *(float2*)(q + orow + lane * 2) = qo;
    *(float2*)(k + orow + lane * 2) = ko;
    *(float2*)(v + orow + lane * 2) = v2;
}

// ----------------------------------------------------------------------------
// Flash attention with tf32 tensor-core MMA (mma.sync.m16n8k8). Unchanged
// from round 6 (passing, ~275us).
// ----------------------------------------------------------------------------
#define PAD 68
#define SK_OFF   0
#define SV_OFF   (64 * PAD)
#define SP_OFF   (2 * 64 * PAD)
#define ATTN_SMEM_FLOATS (3 * 64 * PAD)
#define ATTN_SMEM_BYTES  (ATTN_SMEM_FLOATS * 4)

__global__ __launch_bounds__(128) void attn_mma(
    const float* __restrict__ q, const float* __restrict__ k,
    const float* __restrict__ v, float* __restrict__ o)
{
    extern __shared__ float sm[];
    float* sK = sm + SK_OFF;            // [64][PAD] tf32 bits
    float* sV = sm + SV_OFF;            // [64][PAD] tf32 bits
    float* sP = sm + SP_OFF;            // 4 warps x [16][PAD] tf32 bits

    const int tid  = threadIdx.x;
    const int lane = tid & 31;
    const int warp = tid >> 5;          // 0..3
    const int gid  = lane >> 2;         // 0..7
    const int tig  = lane & 3;          // 0..3
    const int bh = blockIdx.y;
    const int q0 = blockIdx.x * 64;
    const size_t bhoff = (size_t)bh * L_ * D_;
    const float* Q = q + bhoff;
    const float* K = k + bhoff;
    const float* V = v + bhoff;

    const float QSCALE = 0.125f * 1.4426950408889634f;

    const int r0 = q0 + warp * 16 + gid;
    uint32_t qf[8][4];
#pragma unroll
    for (int kk = 0; kk < 8; kk++) {
        qf[kk][0] = f2tf32(Q[(size_t)r0 * D_ + kk * 8 + tig] * QSCALE);
        qf[kk][1] = f2tf32(Q[(size_t)(r0 + 8) * D_ + kk * 8 + tig] * QSCALE);
        qf[kk][2] = f2tf32(Q[(size_t)r0 * D_ + kk * 8 + tig + 4] * QSCALE);
        qf[kk][3] = f2tf32(Q[(size_t)(r0 + 8) * D_ + kk * 8 + tig + 4] * QSCALE);
    }

    float of[8][4];
#pragma unroll
    for (int nt = 0; nt < 8; nt++)
#pragma unroll
        for (int j = 0; j < 4; j++) of[nt][j] = 0.f;

    float m0 = -INFINITY, m1 = -INFINITY;
    float l0 = 0.f, l1 = 0.f;

    uint32_t* sPw = (uint32_t*)(sP + warp * 16 * PAD);

    for (int c0 = 0; c0 < L_; c0 += 64) {
#pragma unroll
        for (int it = 0; it < 8; it++) {
            int idx = tid + it * 128;
            int r = idx >> 4;
            int c4 = idx & 15;
            float4 a = *(const float4*)(K + (size_t)(c0 + r) * D_ + c4 * 4);
            uint4 ua = {f2tf32(a.x), f2tf32(a.y), f2tf32(a.z), f2tf32(a.w)};
            *(uint4*)(&sK[r * PAD + c4 * 4]) = ua;
            float4 bv = *(const float4*)(V + (size_t)(c0 + r) * D_ + c4 * 4);
            uint4 ub = {f2tf32(bv.x), f2tf32(bv.y), f2tf32(bv.z), f2tf32(bv.w)};
            *(uint4*)(&sV[r * PAD + c4 * 4]) = ub;
        }
        __syncthreads();

        float sf[8][4];
#pragma unroll
        for (int nt = 0; nt < 8; nt++)
#pragma unroll
            for (int j = 0; j < 4; j++) sf[nt][j] = 0.f;

        const uint32_t* sKu = (const uint32_t*)sK;
#pragma unroll
        for (int kk = 0; kk < 8; kk++) {
#pragma unroll
            for (int nt = 0; nt < 8; nt++) {
                uint32_t b0 = sKu[(nt * 8 + gid) * PAD + kk * 8 + tig];
                uint32_t b1 = sKu[(nt * 8 + gid) * PAD + kk * 8 + tig + 4];
                mma_tf32(sf[nt], qf[kk], b0, b1);
            }
        }

        float mn0 = m0, mn1 = m1;
#pragma unroll
        for (int nt = 0; nt < 8; nt++) {
            mn0 = fmaxf(mn0, fmaxf(sf[nt][0], sf[nt][1]));
            mn1 = fmaxf(mn1, fmaxf(sf[nt][2], sf[nt][3]));
        }
        mn0 = fmaxf(mn0, __shfl_xor_sync(0xffffffffu, mn0, 1));
        mn0 = fmaxf(mn0, __shfl_xor_sync(0xffffffffu, mn0, 2));
        mn1 = fmaxf(mn1, __shfl_xor_sync(0xffffffffu, mn1, 1));
        mn1 = fmaxf(mn1, __shfl_xor_sync(0xffffffffu, mn1, 2));
        float a0 = exp2f(m0 - mn0);
        float a1 = exp2f(m1 - mn1);
        m0 = mn0; m1 = mn1;
        l0 *= a0; l1 *= a1;

#pragma unroll
        for (int nt = 0; nt < 8; nt++) {
            float p00 = exp2f(sf[nt][0] - m0);
            float p01 = exp2f(sf[nt][1] - m0);
            float p10 = exp2f(sf[nt][2] - m1);
            float p11 = exp2f(sf[nt][3] - m1);
            l0 += p00 + p01;
            l1 += p10 + p11;
            uint2 u0 = {f2tf32(p00), f2tf32(p01)};
            uint2 u1 = {f2tf32(p10), f2tf32(p11)};
            *(uint2*)(&sPw[gid * PAD + nt * 8 + 2 * tig]) = u0;
            *(uint2*)(&sPw[(gid + 8) * PAD + nt * 8 + 2 * tig]) = u1;
            of[nt][0] *= a0; of[nt][1] *= a0;
            of[nt][2] *= a1; of[nt][3] *= a1;
        }
        __syncwarp();

        const uint32_t* sVu = (const uint32_t*)sV;
#pragma unroll
        for (int kk = 0; kk < 8; kk++) {
            uint32_t af[4];
            af[0] = sPw[gid * PAD + kk * 8 + tig];
            af[1] = sPw[(gid + 8) * PAD + kk * 8 + tig];
            af[2] = sPw[gid * PAD + kk * 8 + tig + 4];
            af[3] = sPw[(gid + 8) * PAD + kk * 8 + tig + 4];
#pragma unroll
            for (int nt = 0; nt < 8; nt++) {
                uint32_t b0 = sVu[(kk * 8 + tig) * PAD + nt * 8 + gid];
                uint32_t b1 = sVu[(kk * 8 + tig + 4) * PAD + nt * 8 + gid];
                mma_tf32(of[nt], af, b0, b1);
            }
        }
        __syncthreads();
    }

    l0 += __shfl_xor_sync(0xffffffffu, l0, 1);
    l0 += __shfl_xor_sync(0xffffffffu, l0, 2);
    l1 += __shfl_xor_sync(0xffffffffu, l1, 1);
    l1 += __shfl_xor_sync(0xffffffffu, l1, 2);
    const float inv0 = 1.f / l0;
    const float inv1 = 1.f / l1;

    const int b = bh >> 4;
    const int h = bh & 15;
    float* orow0 = o + (((size_t)(b * L_ + r0)) * H_ + h) * D_;
    float* orow1 = o + (((size_t)(b * L_ + r0 + 8)) * H_ + h) * D_;
#pragma unroll
    for (int nt = 0; nt < 8; nt++) {
        float2 v0 = {of[nt][0] * inv0, of[nt][1] * inv0};
        float2 v1 = {of[nt][2] * inv1, of[nt][3] * inv1};
        *(float2*)(orow0 + nt * 8 + 2 * tig) = v0;
        *(float2*)(orow1 + nt * 8 + 2 * tig) = v1;
    }
}

// ----------------------------------------------------------------------------
// Launch
// ----------------------------------------------------------------------------
extern "C" void kernel_launch(void* const* d_in, const int* in_sizes, int n_in,
                              void* d_out, int out_size)
{
    const float* x      = (const float*)d_in[0];
    const float* pe     = (const float*)d_in[1];
    const float* w_qkv  = (const float*)d_in[2];
    const float* qscale = (const float*)d_in[3];
    const float* kscale = (const float*)d_in[4];
    const float* w_proj = (const float*)d_in[5];
    const float* b_proj = (const float*)d_in[6];
    float* out = (float*)d_out;

    float *p_qkv, *p_q, *p_k, *p_v, *p_o;
    cudaGetSymbolAddress((void**)&p_qkv, g_qkv);
    cudaGetSymbolAddress((void**)&p_q, g_q);
    cudaGetSymbolAddress((void**)&p_k, g_k);
    cudaGetSymbolAddress((void**)&p_v, g_v);
    cudaGetSymbolAddress((void**)&p_o, g_o);

    cudaFuncSetAttribute(attn_mma, cudaFuncAttributeMaxDynamicSharedMemorySize,
                         ATTN_SMEM_BYTES);
    cudaFuncSetAttribute(gemm_tf32s, cudaFuncAttributeMaxDynamicSharedMemorySize,
                         GEMM_SMEM_BYTES);

    // 1. QKV GEMM: [4096,1024] @ [1024,3072]  (split-tf32 tensor cores)
    {
        dim3 grid(3 * DIM_ / 128, BL_ / 128);
        gemm_tf32s<<<grid, 256, GEMM_SMEM_BYTES>>>(x, w_qkv, nullptr, p_qkv,
                                                   BL_, 3 * DIM_, DIM_);
    }
    // 2. RMSNorm + RoPE + split
    {
        int warps = B_ * H_ * L_;              // 65536
        rmsrope_kernel<<<warps * 32 / 256, 256>>>(p_qkv, pe, qscale, kscale,
                                                  p_q, p_k, p_v);
    }
    // 3. Attention (tf32 tensor cores)
    {
        dim3 grid(L_ / 64, BH_);
        attn_mma<<<grid, 128, ATTN_SMEM_BYTES>>>(p_q, p_k, p_v, p_o);
    }
    // 4. Output projection: [4096,1024] @ [1024,1024] + bias (split-tf32)
    {
        dim3 grid(DIM_ / 128, BL_ / 128);
        gemm_tf32s<<<grid, 256, GEMM_SMEM_BYTES>>>(p_o, w_proj, b_proj, out,
                                                   BL_, DIM_, DIM_);
    }
}